// round 5
// baseline (speedup 1.0000x reference)
#include <cuda_runtime.h>
#include <cuda_fp16.h>
#include <cstdint>

#define TS    512
#define NBAT  512
#define HID   128
#define INP   32
#define G4    512
#define NB    8
#define HSTR  136   // padded h_sm row stride (halfs) -> conflict-free B-frag reads
#define XSTR  40    // padded x_sm row stride (halfs)

// ---------------- device-global scratch (no runtime allocation allowed) ----------------
__device__ __half g_WencHH[G4 * HID];          // enc_Whh fp16
__device__ __half g_WencIH[G4 * INP];          // enc_Wih fp16
__device__ __half g_WdecHH[G4 * HID];          // dec_Whh fp16 (decoder step 0)
__device__ __half g_Wcomb [G4 * HID];          // dec_Wih + dec_Whh fp16 (steps >=1, inp==h)
__device__ float  g_benc[G4];                  // enc_bih + enc_bhh
__device__ float  g_bdec[G4];                  // dec_bih + dec_bhh
__device__ __half g_fcW[INP * HID];            // fc_W fp16
__device__ __half g_xT[(size_t)TS * NBAT * INP];         // [t][b][i]  16MB
__device__ __half g_ench[NBAT * HID];          // encoder final h (fp16)
__device__ float  g_encc[NBAT * HID];          // encoder final c (fp32)
__device__ __half g_dech[(size_t)TS * NBAT * HID];       // [t][b][h]  64MB

// ---------------- activations: packed f16x2 tanh (1 MUFU per 2 elements) ----------------
__device__ __forceinline__ __half2 my_h2tanh(__half2 x) {
    uint32_t xi = *reinterpret_cast<uint32_t*>(&x);
    uint32_t ri;
    asm("tanh.approx.f16x2 %0, %1;" : "=r"(ri) : "r"(xi));
    return *reinterpret_cast<__half2*>(&ri);
}
__device__ __forceinline__ __half2 my_h2sig(__half2 x) {
    const __half2 h05 = __float2half2_rn(0.5f);
    __half2 t = my_h2tanh(__hmul2(x, h05));
    return __hfma2(t, h05, h05);      // 0.5*tanh(0.5x)+0.5
}

// ---------------- mma.m16n8k16 row.col f32.f16.f16.f32 ----------------
#define MMA16816(acc, a, b)                                                        \
    asm("mma.sync.aligned.m16n8k16.row.col.f32.f16.f16.f32 "                       \
        "{%0,%1,%2,%3}, {%4,%5,%6,%7}, {%8,%9}, {%0,%1,%2,%3};"                    \
        : "+f"(acc[0]), "+f"(acc[1]), "+f"(acc[2]), "+f"(acc[3])                   \
        : "r"(a[0]), "r"(a[1]), "r"(a[2]), "r"(a[3]), "r"(b[0]), "r"(b[1]))

// ======================= prep: weight conversion =======================
__global__ void prep_weights(const float* __restrict__ eWih, const float* __restrict__ eWhh,
                             const float* __restrict__ ebih, const float* __restrict__ ebhh,
                             const float* __restrict__ dWih, const float* __restrict__ dWhh,
                             const float* __restrict__ dbih, const float* __restrict__ dbhh,
                             const float* __restrict__ fcW) {
    int n = blockIdx.x * blockDim.x + threadIdx.x;
    if (n < G4 * HID) {
        g_WencHH[n] = __float2half(eWhh[n]);
        g_WdecHH[n] = __float2half(dWhh[n]);
        g_Wcomb[n]  = __float2half(dWih[n] + dWhh[n]);
    }
    if (n < G4 * INP) g_WencIH[n] = __float2half(eWih[n]);
    if (n < INP * HID) g_fcW[n] = __float2half(fcW[n]);
    if (n < G4) {
        g_benc[n] = ebih[n] + ebhh[n];
        g_bdec[n] = dbih[n] + dbhh[n];
    }
}

// ======================= prep: x transpose [b][t][i] -> [t][b][i] fp16 =======================
__global__ void prep_x(const float* __restrict__ x) {
    size_t n = (size_t)blockIdx.x * blockDim.x + threadIdx.x;
    if (n < (size_t)TS * NBAT * INP) {
        int i = (int)(n & 31);
        int b = (int)((n >> 5) & 511);
        int t = (int)(n >> 14);
        g_xT[n] = __float2half(x[((size_t)b << 14) + (size_t)t * INP + i]);
    }
}

// ======================= encoder: 512 recurrent steps, weight-stationary =======================
__global__ void __launch_bounds__(256, 1) enc_kernel() {
    __shared__ __half h_sm[2][NB * HSTR];
    __shared__ __half x_sm[2][NB * XSTR];

    const int tid  = threadIdx.x;
    const int w    = tid >> 5;
    const int lane = tid & 31;
    const int g    = lane >> 2;
    const int q    = lane & 3;
    const int bbase = blockIdx.x * NB;

    for (int j = tid; j < NB * HSTR; j += 256) h_sm[0][j] = __float2half(0.0f);

    // ---- stationary A fragments: Whh (8 k-tiles) + Wih (2 k-tiles) ----
    uint32_t aW[4][8][4];
    uint32_t aX[4][2][4];
#pragma unroll
    for (int G = 0; G < 4; G++) {
        const int R = G * 128 + w * 16;
#pragma unroll
        for (int kt = 0; kt < 8; kt++) {
            const int col = kt * 16 + 2 * q;
            aW[G][kt][0] = *(const uint32_t*)&g_WencHH[(R + g) * 128 + col];
            aW[G][kt][1] = *(const uint32_t*)&g_WencHH[(R + g + 8) * 128 + col];
            aW[G][kt][2] = *(const uint32_t*)&g_WencHH[(R + g) * 128 + col + 8];
            aW[G][kt][3] = *(const uint32_t*)&g_WencHH[(R + g + 8) * 128 + col + 8];
        }
#pragma unroll
        for (int kt = 0; kt < 2; kt++) {
            const int col = kt * 16 + 2 * q;
            aX[G][kt][0] = *(const uint32_t*)&g_WencIH[(R + g) * 32 + col];
            aX[G][kt][1] = *(const uint32_t*)&g_WencIH[(R + g + 8) * 32 + col];
            aX[G][kt][2] = *(const uint32_t*)&g_WencIH[(R + g) * 32 + col + 8];
            aX[G][kt][3] = *(const uint32_t*)&g_WencIH[(R + g + 8) * 32 + col + 8];
        }
    }

    float bias[4][2];
#pragma unroll
    for (int G = 0; G < 4; G++) {
        bias[G][0] = g_benc[G * 128 + w * 16 + g];
        bias[G][1] = g_benc[G * 128 + w * 16 + g + 8];
    }

    float c[4] = {0.f, 0.f, 0.f, 0.f};

    if (tid < 128) {
        uint32_t v = *(const uint32_t*)&g_xT[(size_t)bbase * INP + tid * 2];
        int b = tid >> 4, u = tid & 15;
        *(uint32_t*)&x_sm[0][b * XSTR + 2 * u] = v;
    }
    __syncthreads();

    const int r0 = w * 16 + g;
    const int r1 = w * 16 + g + 8;
    const int n0 = 2 * q;        // batch col for j even
    const int n1 = 2 * q + 1;    // batch col for j odd

    for (int t = 0; t < TS; t++) {
        const int cur = t & 1;

        uint32_t xreg = 0;
        if (t < TS - 1 && tid < 128)
            xreg = *(const uint32_t*)&g_xT[(size_t)(t + 1) * (NBAT * INP) + (size_t)bbase * INP + tid * 2];

        uint32_t bf[8][2], bx[2][2];
#pragma unroll
        for (int kt = 0; kt < 8; kt++) {
            bf[kt][0] = *(const uint32_t*)&h_sm[cur][g * HSTR + kt * 16 + 2 * q];
            bf[kt][1] = *(const uint32_t*)&h_sm[cur][g * HSTR + kt * 16 + 2 * q + 8];
        }
#pragma unroll
        for (int kt = 0; kt < 2; kt++) {
            bx[kt][0] = *(const uint32_t*)&x_sm[cur][g * XSTR + kt * 16 + 2 * q];
            bx[kt][1] = *(const uint32_t*)&x_sm[cur][g * XSTR + kt * 16 + 2 * q + 8];
        }

        if (t < TS - 1 && tid < 128) {
            int b = tid >> 4, u = tid & 15;
            *(uint32_t*)&x_sm[cur ^ 1][b * XSTR + 2 * u] = xreg;
        }

        float acc[4][4];
#pragma unroll
        for (int G = 0; G < 4; G++) {
            acc[G][0] = bias[G][0]; acc[G][1] = bias[G][0];
            acc[G][2] = bias[G][1]; acc[G][3] = bias[G][1];
        }
#pragma unroll
        for (int G = 0; G < 4; G++) {
#pragma unroll
            for (int kt = 0; kt < 8; kt++) MMA16816(acc[G], aW[G][kt], bf[kt]);
#pragma unroll
            for (int kt = 0; kt < 2; kt++) MMA16816(acc[G], aX[G][kt], bx[kt]);
        }

        // ---- cell update: gates in f16x2 (1 MUFU / 2 elems), c kept in f32 ----
#pragma unroll
        for (int p = 0; p < 2; p++) {         // p=0 -> j{0,1} (row r0); p=1 -> j{2,3} (row r1)
            const int j0 = 2 * p, j1 = 2 * p + 1;
            __half2 i2 = my_h2sig (__floats2half2_rn(acc[0][j0], acc[0][j1]));
            __half2 f2 = my_h2sig (__floats2half2_rn(acc[1][j0], acc[1][j1]));
            __half2 g2 = my_h2tanh(__floats2half2_rn(acc[2][j0], acc[2][j1]));
            __half2 o2 = my_h2sig (__floats2half2_rn(acc[3][j0], acc[3][j1]));

            float2 fi = __half22float2(i2);
            float2 ff = __half22float2(f2);
            float2 fg = __half22float2(g2);
            c[j0] = fmaf(ff.x, c[j0], fi.x * fg.x);
            c[j1] = fmaf(ff.y, c[j1], fi.y * fg.y);

            __half2 th = my_h2tanh(__floats2half2_rn(c[j0], c[j1]));
            __half2 hv = __hmul2(o2, th);

            const int r = p ? r1 : r0;
            h_sm[cur ^ 1][n0 * HSTR + r] = __low2half(hv);
            h_sm[cur ^ 1][n1 * HSTR + r] = __high2half(hv);
        }
        __syncthreads();   // single barrier per step
    }

    // final h is in h_sm[0]
#pragma unroll
    for (int j = 0; j < 4; j++) {
        int r = (j < 2) ? r0 : r1;
        int n = 2 * q + (j & 1);
        g_encc[(bbase + n) * HID + r] = c[j];
    }
    for (int j = tid; j < NB * HID; j += 256) {
        int b = j >> 7, r = j & 127;
        g_ench[(bbase + b) * HID + r] = h_sm[0][b * HSTR + r];
    }
}

// ======================= decoder: step 0 (Whh) + steps 1..511 (Wcomb); c constant =======================
__global__ void __launch_bounds__(256, 1) dec_kernel() {
    __shared__ __half h_sm[2][NB * HSTR];

    const int tid  = threadIdx.x;
    const int w    = tid >> 5;
    const int lane = tid & 31;
    const int g    = lane >> 2;
    const int q    = lane & 3;
    const int bbase = blockIdx.x * NB;

    const int r0 = w * 16 + g;
    const int r1 = w * 16 + g + 8;
    const int n0 = 2 * q;
    const int n1 = 2 * q + 1;

    uint32_t aW[4][8][4];
    auto load_aW = [&](const __half* Wsrc) {
#pragma unroll
        for (int G = 0; G < 4; G++) {
            const int R = G * 128 + w * 16;
#pragma unroll
            for (int kt = 0; kt < 8; kt++) {
                const int col = kt * 16 + 2 * q;
                aW[G][kt][0] = *(const uint32_t*)&Wsrc[(R + g) * 128 + col];
                aW[G][kt][1] = *(const uint32_t*)&Wsrc[(R + g + 8) * 128 + col];
                aW[G][kt][2] = *(const uint32_t*)&Wsrc[(R + g) * 128 + col + 8];
                aW[G][kt][3] = *(const uint32_t*)&Wsrc[(R + g + 8) * 128 + col + 8];
            }
        }
    };

    float bias[4][2];
#pragma unroll
    for (int G = 0; G < 4; G++) {
        bias[G][0] = g_bdec[G * 128 + w * 16 + g];
        bias[G][1] = g_bdec[G * 128 + w * 16 + g + 8];
    }

    // constant cell state = enc_c, packed half2 per row-pair (decoder resets c every step)
    __half2 c2p[2];
    {
        float cc0 = g_encc[(bbase + n0) * HID + r0];
        float cc1 = g_encc[(bbase + n1) * HID + r0];
        float cc2 = g_encc[(bbase + n0) * HID + r1];
        float cc3 = g_encc[(bbase + n1) * HID + r1];
        c2p[0] = __floats2half2_rn(cc0, cc1);
        c2p[1] = __floats2half2_rn(cc2, cc3);
    }

    // init h_sm[0] = enc_h
    for (int j = tid; j < (NB * HID) / 2; j += 256) {
        uint32_t v = ((const uint32_t*)&g_ench[(size_t)bbase * HID])[j];
        int b = j >> 6, kp = j & 63;
        *(uint32_t*)&h_sm[0][b * HSTR + 2 * kp] = v;
    }
    __syncthreads();

    auto do_step = [&](int t) {
        const int cur = t & 1;
        uint32_t bf[8][2];
#pragma unroll
        for (int kt = 0; kt < 8; kt++) {
            bf[kt][0] = *(const uint32_t*)&h_sm[cur][g * HSTR + kt * 16 + 2 * q];
            bf[kt][1] = *(const uint32_t*)&h_sm[cur][g * HSTR + kt * 16 + 2 * q + 8];
        }

        float acc[4][4];
#pragma unroll
        for (int G = 0; G < 4; G++) {
            acc[G][0] = bias[G][0]; acc[G][1] = bias[G][0];
            acc[G][2] = bias[G][1]; acc[G][3] = bias[G][1];
        }
#pragma unroll
        for (int G = 0; G < 4; G++) {
#pragma unroll
            for (int kt = 0; kt < 8; kt++) MMA16816(acc[G], aW[G][kt], bf[kt]);
        }

        // ---- pure-f16x2 cell update (c constant) ----
#pragma unroll
        for (int p = 0; p < 2; p++) {
            const int j0 = 2 * p, j1 = 2 * p + 1;
            __half2 i2 = my_h2sig (__floats2half2_rn(acc[0][j0], acc[0][j1]));
            __half2 f2 = my_h2sig (__floats2half2_rn(acc[1][j0], acc[1][j1]));
            __half2 g2 = my_h2tanh(__floats2half2_rn(acc[2][j0], acc[2][j1]));
            __half2 o2 = my_h2sig (__floats2half2_rn(acc[3][j0], acc[3][j1]));

            __half2 cn = __hfma2(f2, c2p[p], __hmul2(i2, g2));
            __half2 hv = __hmul2(o2, my_h2tanh(cn));

            const int r = p ? r1 : r0;
            h_sm[cur ^ 1][n0 * HSTR + r] = __low2half(hv);
            h_sm[cur ^ 1][n1 * HSTR + r] = __high2half(hv);
        }
        __syncthreads();   // single barrier per step

        // stream h_{t+1} (frame t hidden) to global, coalesced (off critical path)
        for (int j2 = tid; j2 < (NB * HID) / 2; j2 += 256) {
            int b = j2 >> 6, kp = j2 & 63;
            uint32_t v = *(const uint32_t*)&h_sm[cur ^ 1][b * HSTR + 2 * kp];
            ((uint32_t*)&g_dech[(size_t)t * (NBAT * HID) + (size_t)bbase * HID])[j2] = v;
        }
    };

    // step 0: input is zero -> gates = dec_Whh @ enc_h
    load_aW(g_WdecHH);
    do_step(0);

    // steps 1..511: inp == h -> combined weights; same A registers
    load_aW(g_Wcomb);
    for (int t = 1; t < TS; t++) do_step(t);
}

// ======================= FC head: out[b][t][i] = dec_h[t][b][:] @ fcW^T + fc_b =======================
__global__ void __launch_bounds__(256) fc_kernel(const float* __restrict__ fc_b,
                                                 float* __restrict__ out) {
    const int tid  = threadIdx.x;
    const int w    = tid >> 5;
    const int lane = tid & 31;
    const int g    = lane >> 2;
    const int q    = lane & 3;

    uint32_t bfc[4][8][2];
#pragma unroll
    for (int nt = 0; nt < 4; nt++)
#pragma unroll
        for (int kt = 0; kt < 8; kt++) {
            bfc[nt][kt][0] = *(const uint32_t*)&g_fcW[(nt * 8 + g) * HID + kt * 16 + 2 * q];
            bfc[nt][kt][1] = *(const uint32_t*)&g_fcW[(nt * 8 + g) * HID + kt * 16 + 2 * q + 8];
        }
    float fb0[4], fb1[4];
#pragma unroll
    for (int nt = 0; nt < 4; nt++) {
        fb0[nt] = fc_b[nt * 8 + 2 * q];
        fb1[nt] = fc_b[nt * 8 + 2 * q + 1];
    }

    const int warp_global = blockIdx.x * 8 + w;
    const int total_mtiles = (TS * NBAT) / 16;

    for (int mt = warp_global; mt < total_mtiles; mt += 4096) {
        const int row0 = mt * 16 + g;
        const int row1 = row0 + 8;

        float acc[4][4];
#pragma unroll
        for (int nt = 0; nt < 4; nt++) {
            acc[nt][0] = fb0[nt]; acc[nt][1] = fb1[nt];
            acc[nt][2] = fb0[nt]; acc[nt][3] = fb1[nt];
        }
#pragma unroll
        for (int kt = 0; kt < 8; kt++) {
            uint32_t a[4];
            const int col = kt * 16 + 2 * q;
            a[0] = *(const uint32_t*)&g_dech[(size_t)row0 * HID + col];
            a[1] = *(const uint32_t*)&g_dech[(size_t)row1 * HID + col];
            a[2] = *(const uint32_t*)&g_dech[(size_t)row0 * HID + col + 8];
            a[3] = *(const uint32_t*)&g_dech[(size_t)row1 * HID + col + 8];
#pragma unroll
            for (int nt = 0; nt < 4; nt++) MMA16816(acc[nt], a, bfc[nt][kt]);
        }

        {
            const int b0 = row0 & 511, t0 = row0 >> 9;
            const int b1 = row1 & 511, t1 = row1 >> 9;
            float* p0 = out + (size_t)b0 * (TS * INP) + t0 * INP + 2 * q;
            float* p1 = out + (size_t)b1 * (TS * INP) + t1 * INP + 2 * q;
#pragma unroll
            for (int nt = 0; nt < 4; nt++) {
                *(float2*)(p0 + nt * 8) = make_float2(acc[nt][0], acc[nt][1]);
                *(float2*)(p1 + nt * 8) = make_float2(acc[nt][2], acc[nt][3]);
            }
        }
    }
}

// ======================= launch =======================
extern "C" void kernel_launch(void* const* d_in, const int* in_sizes, int n_in,
                              void* d_out, int out_size) {
    const float* x     = (const float*)d_in[0];
    const float* eWih  = (const float*)d_in[1];
    const float* eWhh  = (const float*)d_in[2];
    const float* ebih  = (const float*)d_in[3];
    const float* ebhh  = (const float*)d_in[4];
    const float* dWih  = (const float*)d_in[5];
    const float* dWhh  = (const float*)d_in[6];
    const float* dbih  = (const float*)d_in[7];
    const float* dbhh  = (const float*)d_in[8];
    const float* fcW   = (const float*)d_in[9];
    const float* fcb   = (const float*)d_in[10];
    float* out = (float*)d_out;

    prep_weights<<<(G4 * HID + 255) / 256, 256>>>(eWih, eWhh, ebih, ebhh, dWih, dWhh, dbih, dbhh, fcW);
    prep_x<<<((size_t)TS * NBAT * INP + 255) / 256, 256>>>(x);
    enc_kernel<<<NBAT / NB, 256>>>();
    dec_kernel<<<NBAT / NB, 256>>>();
    fc_kernel<<<512, 256>>>(fcb, out);
}

// round 6
// speedup vs baseline: 1.0217x; 1.0217x over previous
#include <cuda_runtime.h>
#include <cuda_fp16.h>
#include <cstdint>

#define TS    512
#define NBAT  512
#define HID   128
#define INP   32
#define G4    512
#define NB    8
#define HSTR  136   // padded h_sm row stride (halfs) -> conflict-free B-frag reads
#define XSTR  40    // padded x_sm row stride (halfs)

// ---------------- device-global scratch (no runtime allocation allowed) ----------------
__device__ __half g_WencHH[G4 * HID];          // enc_Whh fp16
__device__ __half g_WencIH[G4 * INP];          // enc_Wih fp16
__device__ __half g_WdecHH[G4 * HID];          // dec_Whh fp16 (decoder step 0)
__device__ __half g_Wcomb [G4 * HID];          // dec_Wih + dec_Whh fp16 (steps >=1, inp==h)
__device__ float  g_benc[G4];                  // enc_bih + enc_bhh
__device__ float  g_bdec[G4];                  // dec_bih + dec_bhh
__device__ __half g_fcW[INP * HID];            // fc_W fp16
__device__ __half g_xT[(size_t)TS * NBAT * INP];         // [t][b][i]  16MB
__device__ __half g_ench[NBAT * HID];          // encoder final h (fp16)
__device__ float  g_encc[NBAT * HID];          // encoder final c (fp32)
__device__ __half g_dech[(size_t)TS * NBAT * HID];       // [t][b][h]  64MB

// ---------------- activations: single-MUFU f32 tanh.approx ----------------
__device__ __forceinline__ float tanh_apx(float x) {
    float r; asm("tanh.approx.f32 %0, %1;" : "=f"(r) : "f"(x)); return r;
}
__device__ __forceinline__ float sig_apx(float x) {
    return fmaf(0.5f, tanh_apx(0.5f * x), 0.5f);
}

// ---------------- mma.m16n8k16 row.col f32.f16.f16.f32 ----------------
#define MMA16816(acc, a, b)                                                        \
    asm("mma.sync.aligned.m16n8k16.row.col.f32.f16.f16.f32 "                       \
        "{%0,%1,%2,%3}, {%4,%5,%6,%7}, {%8,%9}, {%0,%1,%2,%3};"                    \
        : "+f"(acc[0]), "+f"(acc[1]), "+f"(acc[2]), "+f"(acc[3])                   \
        : "r"(a[0]), "r"(a[1]), "r"(a[2]), "r"(a[3]), "r"(b[0]), "r"(b[1]))

// ======================= prep: weight conversion =======================
__global__ void prep_weights(const float* __restrict__ eWih, const float* __restrict__ eWhh,
                             const float* __restrict__ ebih, const float* __restrict__ ebhh,
                             const float* __restrict__ dWih, const float* __restrict__ dWhh,
                             const float* __restrict__ dbih, const float* __restrict__ dbhh,
                             const float* __restrict__ fcW) {
    int n = blockIdx.x * blockDim.x + threadIdx.x;
    if (n < G4 * HID) {
        g_WencHH[n] = __float2half(eWhh[n]);
        g_WdecHH[n] = __float2half(dWhh[n]);
        g_Wcomb[n]  = __float2half(dWih[n] + dWhh[n]);
    }
    if (n < G4 * INP) g_WencIH[n] = __float2half(eWih[n]);
    if (n < INP * HID) g_fcW[n] = __float2half(fcW[n]);
    if (n < G4) {
        g_benc[n] = ebih[n] + ebhh[n];
        g_bdec[n] = dbih[n] + dbhh[n];
    }
}

// ======================= prep: x transpose [b][t][i] -> [t][b][i] fp16 =======================
__global__ void prep_x(const float* __restrict__ x) {
    size_t n = (size_t)blockIdx.x * blockDim.x + threadIdx.x;
    if (n < (size_t)TS * NBAT * INP) {
        int i = (int)(n & 31);
        int b = (int)((n >> 5) & 511);
        int t = (int)(n >> 14);
        g_xT[n] = __float2half(x[((size_t)b << 14) + (size_t)t * INP + i]);
    }
}

// ======================= encoder: 512 recurrent steps, weight-stationary =======================
__global__ void __launch_bounds__(256, 1) enc_kernel() {
    __shared__ __half h_sm[2][NB * HSTR];
    __shared__ __half x_sm[2][NB * XSTR];

    const int tid  = threadIdx.x;
    const int w    = tid >> 5;
    const int lane = tid & 31;
    const int g    = lane >> 2;
    const int q    = lane & 3;
    const int bbase = blockIdx.x * NB;

    for (int j = tid; j < NB * HSTR; j += 256) h_sm[0][j] = __float2half(0.0f);

    // ---- stationary A fragments: Whh (8 k-tiles) + Wih (2 k-tiles) ----
    uint32_t aW[4][8][4];
    uint32_t aX[4][2][4];
#pragma unroll
    for (int G = 0; G < 4; G++) {
        const int R = G * 128 + w * 16;
#pragma unroll
        for (int kt = 0; kt < 8; kt++) {
            const int col = kt * 16 + 2 * q;
            aW[G][kt][0] = *(const uint32_t*)&g_WencHH[(R + g) * 128 + col];
            aW[G][kt][1] = *(const uint32_t*)&g_WencHH[(R + g + 8) * 128 + col];
            aW[G][kt][2] = *(const uint32_t*)&g_WencHH[(R + g) * 128 + col + 8];
            aW[G][kt][3] = *(const uint32_t*)&g_WencHH[(R + g + 8) * 128 + col + 8];
        }
#pragma unroll
        for (int kt = 0; kt < 2; kt++) {
            const int col = kt * 16 + 2 * q;
            aX[G][kt][0] = *(const uint32_t*)&g_WencIH[(R + g) * 32 + col];
            aX[G][kt][1] = *(const uint32_t*)&g_WencIH[(R + g + 8) * 32 + col];
            aX[G][kt][2] = *(const uint32_t*)&g_WencIH[(R + g) * 32 + col + 8];
            aX[G][kt][3] = *(const uint32_t*)&g_WencIH[(R + g + 8) * 32 + col + 8];
        }
    }

    float bias[4][2];
#pragma unroll
    for (int G = 0; G < 4; G++) {
        bias[G][0] = g_benc[G * 128 + w * 16 + g];
        bias[G][1] = g_benc[G * 128 + w * 16 + g + 8];
    }

    float c[4] = {0.f, 0.f, 0.f, 0.f};

    if (tid < 128) {
        uint32_t v = *(const uint32_t*)&g_xT[(size_t)bbase * INP + tid * 2];
        int b = tid >> 4, u = tid & 15;
        *(uint32_t*)&x_sm[0][b * XSTR + 2 * u] = v;
    }
    __syncthreads();

    const int r0 = w * 16 + g;
    const int r1 = w * 16 + g + 8;

    for (int t = 0; t < TS; t++) {
        const int cur = t & 1;

        uint32_t xreg = 0;
        if (t < TS - 1 && tid < 128)
            xreg = *(const uint32_t*)&g_xT[(size_t)(t + 1) * (NBAT * INP) + (size_t)bbase * INP + tid * 2];

        uint32_t bf[8][2], bx[2][2];
#pragma unroll
        for (int kt = 0; kt < 8; kt++) {
            bf[kt][0] = *(const uint32_t*)&h_sm[cur][g * HSTR + kt * 16 + 2 * q];
            bf[kt][1] = *(const uint32_t*)&h_sm[cur][g * HSTR + kt * 16 + 2 * q + 8];
        }
#pragma unroll
        for (int kt = 0; kt < 2; kt++) {
            bx[kt][0] = *(const uint32_t*)&x_sm[cur][g * XSTR + kt * 16 + 2 * q];
            bx[kt][1] = *(const uint32_t*)&x_sm[cur][g * XSTR + kt * 16 + 2 * q + 8];
        }

        if (t < TS - 1 && tid < 128) {
            int b = tid >> 4, u = tid & 15;
            *(uint32_t*)&x_sm[cur ^ 1][b * XSTR + 2 * u] = xreg;
        }

        // two accumulator sets -> HMMA dependency depth 4 instead of 8
        float accA[4][4], accB[4][4];
#pragma unroll
        for (int G = 0; G < 4; G++) {
            accA[G][0] = bias[G][0]; accA[G][1] = bias[G][0];
            accA[G][2] = bias[G][1]; accA[G][3] = bias[G][1];
            accB[G][0] = 0.f; accB[G][1] = 0.f; accB[G][2] = 0.f; accB[G][3] = 0.f;
        }
#pragma unroll
        for (int G = 0; G < 4; G++) {
#pragma unroll
            for (int kt = 0; kt < 4; kt++) MMA16816(accA[G], aW[G][kt], bf[kt]);
#pragma unroll
            for (int kt = 4; kt < 8; kt++) MMA16816(accB[G], aW[G][kt], bf[kt]);
#pragma unroll
            for (int kt = 0; kt < 2; kt++) MMA16816(accB[G], aX[G][kt], bx[kt]);
        }
#pragma unroll
        for (int G = 0; G < 4; G++)
#pragma unroll
            for (int j = 0; j < 4; j++) accA[G][j] += accB[G][j];

        // cell update (thread-local)
#pragma unroll
        for (int j = 0; j < 4; j++) {
            float iv = sig_apx(accA[0][j]);
            float fv = sig_apx(accA[1][j]);
            float gv = tanh_apx(accA[2][j]);
            float ov = sig_apx(accA[3][j]);
            c[j] = fmaf(fv, c[j], iv * gv);
            float hv = ov * tanh_apx(c[j]);
            int r = (j < 2) ? r0 : r1;
            int n = 2 * q + (j & 1);
            h_sm[cur ^ 1][n * HSTR + r] = __float2half(hv);
        }
        __syncthreads();   // single barrier per step
    }

    // final h is in h_sm[0]
#pragma unroll
    for (int j = 0; j < 4; j++) {
        int r = (j < 2) ? r0 : r1;
        int n = 2 * q + (j & 1);
        g_encc[(bbase + n) * HID + r] = c[j];
    }
    for (int j = tid; j < NB * HID; j += 256) {
        int b = j >> 7, r = j & 127;
        g_ench[(bbase + b) * HID + r] = h_sm[0][b * HSTR + r];
    }
}

// ======================= decoder: step 0 (Whh) + steps 1..511 (Wcomb); c constant =======================
__global__ void __launch_bounds__(256, 1) dec_kernel() {
    __shared__ __half h_sm[2][NB * HSTR];

    const int tid  = threadIdx.x;
    const int w    = tid >> 5;
    const int lane = tid & 31;
    const int g    = lane >> 2;
    const int q    = lane & 3;
    const int bbase = blockIdx.x * NB;

    const int r0 = w * 16 + g;
    const int r1 = w * 16 + g + 8;

    uint32_t aW[4][8][4];
    auto load_aW = [&](const __half* Wsrc) {
#pragma unroll
        for (int G = 0; G < 4; G++) {
            const int R = G * 128 + w * 16;
#pragma unroll
            for (int kt = 0; kt < 8; kt++) {
                const int col = kt * 16 + 2 * q;
                aW[G][kt][0] = *(const uint32_t*)&Wsrc[(R + g) * 128 + col];
                aW[G][kt][1] = *(const uint32_t*)&Wsrc[(R + g + 8) * 128 + col];
                aW[G][kt][2] = *(const uint32_t*)&Wsrc[(R + g) * 128 + col + 8];
                aW[G][kt][3] = *(const uint32_t*)&Wsrc[(R + g + 8) * 128 + col + 8];
            }
        }
    };

    float bias[4][2];
#pragma unroll
    for (int G = 0; G < 4; G++) {
        bias[G][0] = g_bdec[G * 128 + w * 16 + g];
        bias[G][1] = g_bdec[G * 128 + w * 16 + g + 8];
    }

    // constant cell state = enc_c (decoder resets c every step)
    float c[4];
#pragma unroll
    for (int j = 0; j < 4; j++) {
        int r = (j < 2) ? r0 : r1;
        int n = 2 * q + (j & 1);
        c[j] = g_encc[(bbase + n) * HID + r];
    }

    // init h_sm[0] = enc_h
    for (int j = tid; j < (NB * HID) / 2; j += 256) {
        uint32_t v = ((const uint32_t*)&g_ench[(size_t)bbase * HID])[j];
        int b = j >> 6, kp = j & 63;
        *(uint32_t*)&h_sm[0][b * HSTR + 2 * kp] = v;
    }
    __syncthreads();

    auto do_step = [&](int t) {
        const int cur = t & 1;
        uint32_t bf[8][2];
#pragma unroll
        for (int kt = 0; kt < 8; kt++) {
            bf[kt][0] = *(const uint32_t*)&h_sm[cur][g * HSTR + kt * 16 + 2 * q];
            bf[kt][1] = *(const uint32_t*)&h_sm[cur][g * HSTR + kt * 16 + 2 * q + 8];
        }

        // two accumulator sets -> HMMA dependency depth 4 instead of 8
        float accA[4][4], accB[4][4];
#pragma unroll
        for (int G = 0; G < 4; G++) {
            accA[G][0] = bias[G][0]; accA[G][1] = bias[G][0];
            accA[G][2] = bias[G][1]; accA[G][3] = bias[G][1];
            accB[G][0] = 0.f; accB[G][1] = 0.f; accB[G][2] = 0.f; accB[G][3] = 0.f;
        }
#pragma unroll
        for (int G = 0; G < 4; G++) {
#pragma unroll
            for (int kt = 0; kt < 4; kt++) MMA16816(accA[G], aW[G][kt], bf[kt]);
#pragma unroll
            for (int kt = 4; kt < 8; kt++) MMA16816(accB[G], aW[G][kt], bf[kt]);
        }
#pragma unroll
        for (int G = 0; G < 4; G++)
#pragma unroll
            for (int j = 0; j < 4; j++) accA[G][j] += accB[G][j];

#pragma unroll
        for (int j = 0; j < 4; j++) {
            float iv = sig_apx(accA[0][j]);
            float fv = sig_apx(accA[1][j]);
            float gv = tanh_apx(accA[2][j]);
            float ov = sig_apx(accA[3][j]);
            float cn = fmaf(fv, c[j], iv * gv);   // c constant across steps
            float hv = ov * tanh_apx(cn);
            int r = (j < 2) ? r0 : r1;
            int n = 2 * q + (j & 1);
            h_sm[cur ^ 1][n * HSTR + r] = __float2half(hv);
        }
        __syncthreads();   // single barrier per step

        // stream h_{t+1} (frame t hidden) to global, coalesced (off critical path)
        for (int j2 = tid; j2 < (NB * HID) / 2; j2 += 256) {
            int b = j2 >> 6, kp = j2 & 63;
            uint32_t v = *(const uint32_t*)&h_sm[cur ^ 1][b * HSTR + 2 * kp];
            ((uint32_t*)&g_dech[(size_t)t * (NBAT * HID) + (size_t)bbase * HID])[j2] = v;
        }
    };

    // step 0: input is zero -> gates = dec_Whh @ enc_h
    load_aW(g_WdecHH);
    do_step(0);

    // steps 1..511: inp == h -> combined weights; same A registers
    load_aW(g_Wcomb);
    for (int t = 1; t < TS; t++) do_step(t);
}

// ======================= FC head: out[b][t][i] = dec_h[t][b][:] @ fcW^T + fc_b =======================
__global__ void __launch_bounds__(256) fc_kernel(const float* __restrict__ fc_b,
                                                 float* __restrict__ out) {
    const int tid  = threadIdx.x;
    const int w    = tid >> 5;
    const int lane = tid & 31;
    const int g    = lane >> 2;
    const int q    = lane & 3;

    uint32_t bfc[4][8][2];
#pragma unroll
    for (int nt = 0; nt < 4; nt++)
#pragma unroll
        for (int kt = 0; kt < 8; kt++) {
            bfc[nt][kt][0] = *(const uint32_t*)&g_fcW[(nt * 8 + g) * HID + kt * 16 + 2 * q];
            bfc[nt][kt][1] = *(const uint32_t*)&g_fcW[(nt * 8 + g) * HID + kt * 16 + 2 * q + 8];
        }
    float fb0[4], fb1[4];
#pragma unroll
    for (int nt = 0; nt < 4; nt++) {
        fb0[nt] = fc_b[nt * 8 + 2 * q];
        fb1[nt] = fc_b[nt * 8 + 2 * q + 1];
    }

    const int warp_global = blockIdx.x * 8 + w;
    const int total_mtiles = (TS * NBAT) / 16;

    for (int mt = warp_global; mt < total_mtiles; mt += 4096) {
        const int row0 = mt * 16 + g;
        const int row1 = row0 + 8;

        float acc[4][4];
#pragma unroll
        for (int nt = 0; nt < 4; nt++) {
            acc[nt][0] = fb0[nt]; acc[nt][1] = fb1[nt];
            acc[nt][2] = fb0[nt]; acc[nt][3] = fb1[nt];
        }
#pragma unroll
        for (int kt = 0; kt < 8; kt++) {
            uint32_t a[4];
            const int col = kt * 16 + 2 * q;
            a[0] = *(const uint32_t*)&g_dech[(size_t)row0 * HID + col];
            a[1] = *(const uint32_t*)&g_dech[(size_t)row1 * HID + col];
            a[2] = *(const uint32_t*)&g_dech[(size_t)row0 * HID + col + 8];
            a[3] = *(const uint32_t*)&g_dech[(size_t)row1 * HID + col + 8];
#pragma unroll
            for (int nt = 0; nt < 4; nt++) MMA16816(acc[nt], a, bfc[nt][kt]);
        }

        {
            const int b0 = row0 & 511, t0 = row0 >> 9;
            const int b1 = row1 & 511, t1 = row1 >> 9;
            float* p0 = out + (size_t)b0 * (TS * INP) + t0 * INP + 2 * q;
            float* p1 = out + (size_t)b1 * (TS * INP) + t1 * INP + 2 * q;
#pragma unroll
            for (int nt = 0; nt < 4; nt++) {
                *(float2*)(p0 + nt * 8) = make_float2(acc[nt][0], acc[nt][1]);
                *(float2*)(p1 + nt * 8) = make_float2(acc[nt][2], acc[nt][3]);
            }
        }
    }
}

// ======================= launch =======================
extern "C" void kernel_launch(void* const* d_in, const int* in_sizes, int n_in,
                              void* d_out, int out_size) {
    const float* x     = (const float*)d_in[0];
    const float* eWih  = (const float*)d_in[1];
    const float* eWhh  = (const float*)d_in[2];
    const float* ebih  = (const float*)d_in[3];
    const float* ebhh  = (const float*)d_in[4];
    const float* dWih  = (const float*)d_in[5];
    const float* dWhh  = (const float*)d_in[6];
    const float* dbih  = (const float*)d_in[7];
    const float* dbhh  = (const float*)d_in[8];
    const float* fcW   = (const float*)d_in[9];
    const float* fcb   = (const float*)d_in[10];
    float* out = (float*)d_out;

    prep_weights<<<(G4 * HID + 255) / 256, 256>>>(eWih, eWhh, ebih, ebhh, dWih, dWhh, dbih, dbhh, fcW);
    prep_x<<<((size_t)TS * NBAT * INP + 255) / 256, 256>>>(x);
    enc_kernel<<<NBAT / NB, 256>>>();
    dec_kernel<<<NBAT / NB, 256>>>();
    fc_kernel<<<512, 256>>>(fcb, out);
}

// round 7
// speedup vs baseline: 1.0456x; 1.0234x over previous
#include <cuda_runtime.h>
#include <cuda_fp16.h>
#include <cstdint>

#define TS    512
#define NBAT  512
#define HID   128
#define INP   32
#define G4    512
#define NB    8
#define HSTR  136   // padded h_sm row stride (halfs) -> conflict-free B-frag reads
#define XSTR  40    // padded x_sm row stride (halfs)

// ---------------- device-global scratch (no runtime allocation allowed) ----------------
__device__ __half g_WencHH[G4 * HID];          // enc_Whh fp16
__device__ __half g_WencIH[G4 * INP];          // enc_Wih fp16
__device__ __half g_WdecHH[G4 * HID];          // dec_Whh fp16 (decoder step 0)
__device__ __half g_Wcomb [G4 * HID];          // dec_Wih + dec_Whh fp16 (steps >=1, inp==h)
__device__ float  g_benc[G4];                  // enc_bih + enc_bhh
__device__ float  g_bdec[G4];                  // dec_bih + dec_bhh
__device__ __half g_fcW[INP * HID];            // fc_W fp16
__device__ __half g_xT[(size_t)TS * NBAT * INP];         // [t][b][i]  16MB
__device__ __half g_ench[NBAT * HID];          // encoder final h (fp16)
__device__ float  g_encc[NBAT * HID];          // encoder final c (fp32)
__device__ __half g_dech[(size_t)TS * NBAT * HID];       // [t][b][h]  64MB

// ---------------- activations ----------------
__device__ __forceinline__ float tanh_apx(float x) {
    float r; asm("tanh.approx.f32 %0, %1;" : "=f"(r) : "f"(x)); return r;
}
__device__ __forceinline__ float sig_apx(float x) {
    return fmaf(0.5f, tanh_apx(0.5f * x), 0.5f);
}
__device__ __forceinline__ uint32_t u2tanh(uint32_t x) {
    uint32_t r; asm("tanh.approx.f16x2 %0, %1;" : "=r"(r) : "r"(x)); return r;
}
__device__ __forceinline__ __half2 uh2(uint32_t u) { return *reinterpret_cast<__half2*>(&u); }
__device__ __forceinline__ uint32_t h2u(__half2 h) { return *reinterpret_cast<uint32_t*>(&h); }
__device__ __forceinline__ __half2 h2tanh_(__half2 x) { return uh2(u2tanh(h2u(x))); }
__device__ __forceinline__ __half2 h2sig_(__half2 x) {
    const __half2 h05 = __float2half2_rn(0.5f);
    return __hfma2(h2tanh_(__hmul2(x, h05)), h05, h05);
}

// ---------------- mma.m16n8k16 f32-acc and f16-acc ----------------
#define MMA16816(acc, a, b)                                                        \
    asm("mma.sync.aligned.m16n8k16.row.col.f32.f16.f16.f32 "                       \
        "{%0,%1,%2,%3}, {%4,%5,%6,%7}, {%8,%9}, {%0,%1,%2,%3};"                    \
        : "+f"(acc[0]), "+f"(acc[1]), "+f"(acc[2]), "+f"(acc[3])                   \
        : "r"(a[0]), "r"(a[1]), "r"(a[2]), "r"(a[3]), "r"(b[0]), "r"(b[1]))

#define MMA16816H(acc, a, b)                                                       \
    asm("mma.sync.aligned.m16n8k16.row.col.f16.f16.f16.f16 "                       \
        "{%0,%1}, {%2,%3,%4,%5}, {%6,%7}, {%0,%1};"                                \
        : "+r"(acc[0]), "+r"(acc[1])                                               \
        : "r"(a[0]), "r"(a[1]), "r"(a[2]), "r"(a[3]), "r"(b[0]), "r"(b[1]))

// ======================= prep: weight conversion =======================
__global__ void prep_weights(const float* __restrict__ eWih, const float* __restrict__ eWhh,
                             const float* __restrict__ ebih, const float* __restrict__ ebhh,
                             const float* __restrict__ dWih, const float* __restrict__ dWhh,
                             const float* __restrict__ dbih, const float* __restrict__ dbhh,
                             const float* __restrict__ fcW) {
    int n = blockIdx.x * blockDim.x + threadIdx.x;
    if (n < G4 * HID) {
        g_WencHH[n] = __float2half(eWhh[n]);
        g_WdecHH[n] = __float2half(dWhh[n]);
        g_Wcomb[n]  = __float2half(dWih[n] + dWhh[n]);
    }
    if (n < G4 * INP) g_WencIH[n] = __float2half(eWih[n]);
    if (n < INP * HID) g_fcW[n] = __float2half(fcW[n]);
    if (n < G4) {
        g_benc[n] = ebih[n] + ebhh[n];
        g_bdec[n] = dbih[n] + dbhh[n];
    }
}

// ======================= prep: x transpose [b][t][i] -> [t][b][i] fp16 =======================
__global__ void prep_x(const float* __restrict__ x) {
    size_t n = (size_t)blockIdx.x * blockDim.x + threadIdx.x;
    if (n < (size_t)TS * NBAT * INP) {
        int i = (int)(n & 31);
        int b = (int)((n >> 5) & 511);
        int t = (int)(n >> 14);
        g_xT[n] = __float2half(x[((size_t)b << 14) + (size_t)t * INP + i]);
    }
}

// ======================= encoder: f32-acc path (proven precision), 1 bar/step =======================
__global__ void __launch_bounds__(256, 1) enc_kernel() {
    __shared__ __half h_sm[2][NB * HSTR];
    __shared__ __half x_sm[2][NB * XSTR];

    const int tid  = threadIdx.x;
    const int w    = tid >> 5;
    const int lane = tid & 31;
    const int g    = lane >> 2;
    const int q    = lane & 3;
    const int bbase = blockIdx.x * NB;

    for (int j = tid; j < NB * HSTR; j += 256) h_sm[0][j] = __float2half(0.0f);

    uint32_t aW[4][8][4];
    uint32_t aX[4][2][4];
#pragma unroll
    for (int G = 0; G < 4; G++) {
        const int R = G * 128 + w * 16;
#pragma unroll
        for (int kt = 0; kt < 8; kt++) {
            const int col = kt * 16 + 2 * q;
            aW[G][kt][0] = *(const uint32_t*)&g_WencHH[(R + g) * 128 + col];
            aW[G][kt][1] = *(const uint32_t*)&g_WencHH[(R + g + 8) * 128 + col];
            aW[G][kt][2] = *(const uint32_t*)&g_WencHH[(R + g) * 128 + col + 8];
            aW[G][kt][3] = *(const uint32_t*)&g_WencHH[(R + g + 8) * 128 + col + 8];
        }
#pragma unroll
        for (int kt = 0; kt < 2; kt++) {
            const int col = kt * 16 + 2 * q;
            aX[G][kt][0] = *(const uint32_t*)&g_WencIH[(R + g) * 32 + col];
            aX[G][kt][1] = *(const uint32_t*)&g_WencIH[(R + g + 8) * 32 + col];
            aX[G][kt][2] = *(const uint32_t*)&g_WencIH[(R + g) * 32 + col + 8];
            aX[G][kt][3] = *(const uint32_t*)&g_WencIH[(R + g + 8) * 32 + col + 8];
        }
    }

    float bias[4][2];
#pragma unroll
    for (int G = 0; G < 4; G++) {
        bias[G][0] = g_benc[G * 128 + w * 16 + g];
        bias[G][1] = g_benc[G * 128 + w * 16 + g + 8];
    }

    float c[4] = {0.f, 0.f, 0.f, 0.f};

    if (tid < 128) {
        uint32_t v = *(const uint32_t*)&g_xT[(size_t)bbase * INP + tid * 2];
        int b = tid >> 4, u = tid & 15;
        *(uint32_t*)&x_sm[0][b * XSTR + 2 * u] = v;
    }
    __syncthreads();

    const int r0 = w * 16 + g;
    const int r1 = w * 16 + g + 8;

    for (int t = 0; t < TS; t++) {
        const int cur = t & 1;

        uint32_t xreg = 0;
        if (t < TS - 1 && tid < 128)
            xreg = *(const uint32_t*)&g_xT[(size_t)(t + 1) * (NBAT * INP) + (size_t)bbase * INP + tid * 2];

        uint32_t bf[8][2], bx[2][2];
#pragma unroll
        for (int kt = 0; kt < 8; kt++) {
            bf[kt][0] = *(const uint32_t*)&h_sm[cur][g * HSTR + kt * 16 + 2 * q];
            bf[kt][1] = *(const uint32_t*)&h_sm[cur][g * HSTR + kt * 16 + 2 * q + 8];
        }
#pragma unroll
        for (int kt = 0; kt < 2; kt++) {
            bx[kt][0] = *(const uint32_t*)&x_sm[cur][g * XSTR + kt * 16 + 2 * q];
            bx[kt][1] = *(const uint32_t*)&x_sm[cur][g * XSTR + kt * 16 + 2 * q + 8];
        }

        if (t < TS - 1 && tid < 128) {
            int b = tid >> 4, u = tid & 15;
            *(uint32_t*)&x_sm[cur ^ 1][b * XSTR + 2 * u] = xreg;
        }

        float acc[4][4];
#pragma unroll
        for (int G = 0; G < 4; G++) {
            acc[G][0] = bias[G][0]; acc[G][1] = bias[G][0];
            acc[G][2] = bias[G][1]; acc[G][3] = bias[G][1];
        }
#pragma unroll
        for (int G = 0; G < 4; G++) {
#pragma unroll
            for (int kt = 0; kt < 8; kt++) MMA16816(acc[G], aW[G][kt], bf[kt]);
#pragma unroll
            for (int kt = 0; kt < 2; kt++) MMA16816(acc[G], aX[G][kt], bx[kt]);
        }

#pragma unroll
        for (int j = 0; j < 4; j++) {
            float iv = sig_apx(acc[0][j]);
            float fv = sig_apx(acc[1][j]);
            float gv = tanh_apx(acc[2][j]);
            float ov = sig_apx(acc[3][j]);
            c[j] = fmaf(fv, c[j], iv * gv);
            float hv = ov * tanh_apx(c[j]);
            int r = (j < 2) ? r0 : r1;
            int n = 2 * q + (j & 1);
            h_sm[cur ^ 1][n * HSTR + r] = __float2half(hv);
        }
        __syncthreads();   // single barrier per step
    }

#pragma unroll
    for (int j = 0; j < 4; j++) {
        int r = (j < 2) ? r0 : r1;
        int n = 2 * q + (j & 1);
        g_encc[(bbase + n) * HID + r] = c[j];
    }
    for (int j = tid; j < NB * HID; j += 256) {
        int b = j >> 7, r = j & 127;
        g_ench[(bbase + b) * HID + r] = h_sm[0][b * HSTR + r];
    }
}

// ======================= decoder: f16-acc MMA, pure-half2 cell, reg->gmem streaming =======================
__global__ void __launch_bounds__(256, 1) dec_kernel() {
    __shared__ __half h_sm[2][NB * HSTR];

    const int tid  = threadIdx.x;
    const int w    = tid >> 5;
    const int lane = tid & 31;
    const int g    = lane >> 2;
    const int q    = lane & 3;
    const int bbase = blockIdx.x * NB;

    const int r0 = w * 16 + g;
    const int r1 = w * 16 + g + 8;
    const int n0 = 2 * q;
    const int n1 = 2 * q + 1;

    uint32_t aW[4][8][4];
    auto load_aW = [&](const __half* Wsrc) {
#pragma unroll
        for (int G = 0; G < 4; G++) {
            const int R = G * 128 + w * 16;
#pragma unroll
            for (int kt = 0; kt < 8; kt++) {
                const int col = kt * 16 + 2 * q;
                aW[G][kt][0] = *(const uint32_t*)&Wsrc[(R + g) * 128 + col];
                aW[G][kt][1] = *(const uint32_t*)&Wsrc[(R + g + 8) * 128 + col];
                aW[G][kt][2] = *(const uint32_t*)&Wsrc[(R + g) * 128 + col + 8];
                aW[G][kt][3] = *(const uint32_t*)&Wsrc[(R + g + 8) * 128 + col + 8];
            }
        }
    };

    // bias as broadcast half2 (row-dependent only); [G][p] p=0 -> row r0, p=1 -> row r1
    uint32_t bias2[4][2];
#pragma unroll
    for (int G = 0; G < 4; G++) {
        bias2[G][0] = h2u(__half2half2(__float2half_rn(g_bdec[G * 128 + r0])));
        bias2[G][1] = h2u(__half2half2(__float2half_rn(g_bdec[G * 128 + r1])));
    }

    // constant cell state = enc_c packed half2 (n0,n1) per row: [p]
    __half2 c2p[2];
    c2p[0] = __floats2half2_rn(g_encc[(bbase + n0) * HID + r0], g_encc[(bbase + n1) * HID + r0]);
    c2p[1] = __floats2half2_rn(g_encc[(bbase + n0) * HID + r1], g_encc[(bbase + n1) * HID + r1]);

    // init h_sm[0] = enc_h
    for (int j = tid; j < (NB * HID) / 2; j += 256) {
        uint32_t v = ((const uint32_t*)&g_ench[(size_t)bbase * HID])[j];
        int b = j >> 6, kp = j & 63;
        *(uint32_t*)&h_sm[0][b * HSTR + 2 * kp] = v;
    }
    __syncthreads();

    auto do_step = [&](int t) {
        const int cur = t & 1;
        uint32_t bf[8][2];
#pragma unroll
        for (int kt = 0; kt < 8; kt++) {
            bf[kt][0] = *(const uint32_t*)&h_sm[cur][g * HSTR + kt * 16 + 2 * q];
            bf[kt][1] = *(const uint32_t*)&h_sm[cur][g * HSTR + kt * 16 + 2 * q + 8];
        }

        // f16 accumulators: acc[G][p] is half2 (n0,n1) for row rp
        uint32_t acc[4][2];
#pragma unroll
        for (int G = 0; G < 4; G++) { acc[G][0] = bias2[G][0]; acc[G][1] = bias2[G][1]; }
#pragma unroll
        for (int G = 0; G < 4; G++)
#pragma unroll
            for (int kt = 0; kt < 8; kt++) MMA16816H(acc[G], aW[G][kt], bf[kt]);

        // ---- pure half2 cell update: zero converts ----
        __half* dst = &g_dech[(size_t)t * (NBAT * HID) + (size_t)bbase * HID];
#pragma unroll
        for (int p = 0; p < 2; p++) {
            __half2 i2 = h2sig_ (uh2(acc[0][p]));
            __half2 f2 = h2sig_ (uh2(acc[1][p]));
            __half2 g2 = h2tanh_(uh2(acc[2][p]));
            __half2 o2 = h2sig_ (uh2(acc[3][p]));
            __half2 cn = __hfma2(f2, c2p[p], __hmul2(i2, g2));
            __half2 hv = __hmul2(o2, h2tanh_(cn));

            const int r = p ? r1 : r0;
            __half lo = __low2half(hv), hi = __high2half(hv);
            h_sm[cur ^ 1][n0 * HSTR + r] = lo;
            h_sm[cur ^ 1][n1 * HSTR + r] = hi;
            // stream to gmem straight from registers (fire-and-forget, pre-barrier)
            dst[n0 * HID + r] = lo;
            dst[n1 * HID + r] = hi;
        }
        __syncthreads();   // single barrier per step
    };

    // step 0: input is zero -> gates = dec_Whh @ enc_h
    load_aW(g_WdecHH);
    do_step(0);

    // steps 1..511: inp == h -> combined weights; same A registers
    load_aW(g_Wcomb);
    for (int t = 1; t < TS; t++) do_step(t);
}

// ======================= FC head: out[b][t][i] = dec_h[t][b][:] @ fcW^T + fc_b =======================
__global__ void __launch_bounds__(256) fc_kernel(const float* __restrict__ fc_b,
                                                 float* __restrict__ out) {
    const int tid  = threadIdx.x;
    const int w    = tid >> 5;
    const int lane = tid & 31;
    const int g    = lane >> 2;
    const int q    = lane & 3;

    uint32_t bfc[4][8][2];
#pragma unroll
    for (int nt = 0; nt < 4; nt++)
#pragma unroll
        for (int kt = 0; kt < 8; kt++) {
            bfc[nt][kt][0] = *(const uint32_t*)&g_fcW[(nt * 8 + g) * HID + kt * 16 + 2 * q];
            bfc[nt][kt][1] = *(const uint32_t*)&g_fcW[(nt * 8 + g) * HID + kt * 16 + 2 * q + 8];
        }
    float fb0[4], fb1[4];
#pragma unroll
    for (int nt = 0; nt < 4; nt++) {
        fb0[nt] = fc_b[nt * 8 + 2 * q];
        fb1[nt] = fc_b[nt * 8 + 2 * q + 1];
    }

    const int warp_global = blockIdx.x * 8 + w;
    const int total_mtiles = (TS * NBAT) / 16;

    for (int mt = warp_global; mt < total_mtiles; mt += 4096) {
        const int row0 = mt * 16 + g;
        const int row1 = row0 + 8;

        float acc[4][4];
#pragma unroll
        for (int nt = 0; nt < 4; nt++) {
            acc[nt][0] = fb0[nt]; acc[nt][1] = fb1[nt];
            acc[nt][2] = fb0[nt]; acc[nt][3] = fb1[nt];
        }
#pragma unroll
        for (int kt = 0; kt < 8; kt++) {
            uint32_t a[4];
            const int col = kt * 16 + 2 * q;
            a[0] = *(const uint32_t*)&g_dech[(size_t)row0 * HID + col];
            a[1] = *(const uint32_t*)&g_dech[(size_t)row1 * HID + col];
            a[2] = *(const uint32_t*)&g_dech[(size_t)row0 * HID + col + 8];
            a[3] = *(const uint32_t*)&g_dech[(size_t)row1 * HID + col + 8];
#pragma unroll
            for (int nt = 0; nt < 4; nt++) MMA16816(acc[nt], a, bfc[nt][kt]);
        }

        {
            const int b0 = row0 & 511, t0 = row0 >> 9;
            const int b1 = row1 & 511, t1 = row1 >> 9;
            float* p0 = out + (size_t)b0 * (TS * INP) + t0 * INP + 2 * q;
            float* p1 = out + (size_t)b1 * (TS * INP) + t1 * INP + 2 * q;
#pragma unroll
            for (int nt = 0; nt < 4; nt++) {
                *(float2*)(p0 + nt * 8) = make_float2(acc[nt][0], acc[nt][1]);
                *(float2*)(p1 + nt * 8) = make_float2(acc[nt][2], acc[nt][3]);
            }
        }
    }
}

// ======================= launch =======================
extern "C" void kernel_launch(void* const* d_in, const int* in_sizes, int n_in,
                              void* d_out, int out_size) {
    const float* x     = (const float*)d_in[0];
    const float* eWih  = (const float*)d_in[1];
    const float* eWhh  = (const float*)d_in[2];
    const float* ebih  = (const float*)d_in[3];
    const float* ebhh  = (const float*)d_in[4];
    const float* dWih  = (const float*)d_in[5];
    const float* dWhh  = (const float*)d_in[6];
    const float* dbih  = (const float*)d_in[7];
    const float* dbhh  = (const float*)d_in[8];
    const float* fcW   = (const float*)d_in[9];
    const float* fcb   = (const float*)d_in[10];
    float* out = (float*)d_out;

    prep_weights<<<(G4 * HID + 255) / 256, 256>>>(eWih, eWhh, ebih, ebhh, dWih, dWhh, dbih, dbhh, fcW);
    prep_x<<<((size_t)TS * NBAT * INP + 255) / 256, 256>>>(x);
    enc_kernel<<<NBAT / NB, 256>>>();
    dec_kernel<<<NBAT / NB, 256>>>();
    fc_kernel<<<512, 256>>>(fcb, out);
}